// round 3
// baseline (speedup 1.0000x reference)
#include <cuda_runtime.h>

#define NVW   9
#define HSZ   480
#define WSZ   640
#define NPIX  (HSZ*WSZ)
#define GD    96
#define NCELL (GD*GD*GD)
#define MAXN  400000
#define BIGF  1e30f

// ---- scratch (static device globals; no allocation at runtime) ----
__device__ int          g_last[NCELL];
__device__ float        g_grid[NCELL];
__device__ float        g_pw[MAXN*3];
__device__ float        g_nraw[MAXN*3];
__device__ unsigned int g_dflat[NVW*NPIX];      // z-buffer as float bits (all >= 0)
__device__ float        g_nsum[NVW*NPIX*3];
__device__ float        g_ncnt[NVW*NPIX];
__device__ unsigned int g_dmin[NVW], g_tmin[NVW];   // mins of raw images
__device__ unsigned int g_drng[NVW], g_trng[NVW];   // max of (x - min) (shifted)
__device__ float        g_lsum[NVW];
__device__ int          g_vcnt[NVW];

// XLA:CPU emitted dot (no FMA contraction, left-assoc, strict rn):
//   ((p0*m0 + p1*m1) + p2*m2)
__device__ __forceinline__ float dotrow(const float* M, float px, float py, float pz) {
    return __fadd_rn(__fadd_rn(__fmul_rn(px, M[0]), __fmul_rn(py, M[1])),
                     __fmul_rn(pz, M[2]));
}

// u_f = (fx * x) / zs + cx, strictly left-assoc IEEE
__device__ __forceinline__ int proj_pix(float f, float c, float x, float zs) {
    return __float2int_rn(__fadd_rn(__fdiv_rn(__fmul_rn(f, x), zs), c));
}

// ---------------- init (re-run every launch: graph-replay safe) -----------
__global__ void k_init() {
    int i = blockIdx.x * blockDim.x + threadIdx.x;
    unsigned int big = __float_as_uint(BIGF);
    if (i < NVW * NPIX) {
        g_dflat[i]    = big;
        g_ncnt[i]     = 0.f;
        g_nsum[3*i+0] = 0.f;
        g_nsum[3*i+1] = 0.f;
        g_nsum[3*i+2] = 0.f;
    }
    if (i < NCELL) g_last[i] = -1;
    if (i < NVW) {
        g_dmin[i] = big; g_tmin[i] = big;
        g_drng[i] = 0u;  g_trng[i] = 0u;
        g_lsum[i] = 0.f; g_vcnt[i] = 0;
    }
}

// ------------- scatter: last-write-wins index per cell + p_world ----------
__global__ void k_scatter(const int* __restrict__ coords,
                          const float* __restrict__ origin, int n) {
    int i = blockIdx.x * blockDim.x + threadIdx.x;
    if (i >= n) return;
    int c1 = coords[4*i+1], c2 = coords[4*i+2], c3 = coords[4*i+3];
    int cell = (c3 * GD + c2) * GD + c1;
    atomicMax(&g_last[cell], i);   // emulates sequential .at[].set (last wins)
    g_pw[3*i+0] = __fadd_rn((float)c3, __ldg(&origin[0]));
    g_pw[3*i+1] = __fadd_rn((float)c2, __ldg(&origin[1]));
    g_pw[3*i+2] = __fadd_rn((float)c1, __ldg(&origin[2]));
}

__global__ void k_grid(const float* __restrict__ sdf) {
    int c = blockIdx.x * blockDim.x + threadIdx.x;
    if (c >= NCELL) return;
    int idx = g_last[c];
    g_grid[c] = (idx >= 0) ? __ldg(&sdf[idx]) : 0.f;
}

// ------------- central-difference normals at each point -------------------
__global__ void k_normals(const int* __restrict__ coords, int n) {
    int i = blockIdx.x * blockDim.x + threadIdx.x;
    if (i >= n) return;
    int c1 = coords[4*i+1], c2 = coords[4*i+2], c3 = coords[4*i+3];
    float nx = 0.f, ny = 0.f, nz = 0.f;
    if (c3 >= 1 && c3 <= GD-2 && c2 >= 1 && c2 <= GD-2 && c1 >= 1 && c1 <= GD-2) {
        int base = (c3 * GD + c2) * GD + c1;
        nx = __fsub_rn(g_grid[base + 1],     g_grid[base - 1]);
        ny = __fsub_rn(g_grid[base + GD],    g_grid[base - GD]);
        nz = __fsub_rn(g_grid[base + GD*GD], g_grid[base - GD*GD]);
    }
    g_nraw[3*i+0] = nx; g_nraw[3*i+1] = ny; g_nraw[3*i+2] = nz;
}

// ---------------- per-view constants into shared --------------------------
__device__ __forceinline__ void load_view_consts(const float* __restrict__ vm,
                                                 const float* __restrict__ intr,
                                                 float* s_vm, float* s_in) {
    int t = threadIdx.x;
    if (t < NVW * 12) s_vm[t] = vm[(t / 12) * 16 + (t % 12)];   // rows 0..2 of 4x4
    if (t < NVW * 4) {
        int v = t >> 2, k = t & 3;
        int off = (k == 0) ? 0 : (k == 1) ? 5 : (k == 2) ? 2 : 6; // fx,fy,cx,cy
        s_in[t] = intr[v * 16 + off];
    }
    __syncthreads();
}

// ---------------- pass 1: z-buffer atomicMin -------------------------------
__global__ void k_project(const float* __restrict__ vm,
                          const float* __restrict__ intr, int n) {
    __shared__ float s_vm[NVW * 12];
    __shared__ float s_in[NVW * 4];
    load_view_consts(vm, intr, s_vm, s_in);
    int i = blockIdx.x * blockDim.x + threadIdx.x;
    if (i >= n) return;
    float px = g_pw[3*i], py = g_pw[3*i+1], pz = g_pw[3*i+2];
    for (int v = 0; v < NVW; v++) {
        const float* M = &s_vm[v * 12];
        float x = __fadd_rn(dotrow(M,     px, py, pz), M[3]);
        float y = __fadd_rn(dotrow(M + 4, px, py, pz), M[7]);
        float z = __fadd_rn(dotrow(M + 8, px, py, pz), M[11]);
        float zs = (fabsf(z) < 1e-6f) ? 1e-6f : z;
        int u = proj_pix(s_in[v*4+0], s_in[v*4+2], x, zs);
        int w = proj_pix(s_in[v*4+1], s_in[v*4+3], y, zs);
        if (z > 0.025f && z < 100.0f && u >= 0 && u < WSZ && w >= 0 && w < HSZ)
            atomicMin(&g_dflat[v * NPIX + w * WSZ + u], __float_as_uint(z));
    }
}

// ---------------- pass 2: winner test + normal splat -----------------------
__global__ void k_splat(const float* __restrict__ vm,
                        const float* __restrict__ intr, int n) {
    __shared__ float s_vm[NVW * 12];
    __shared__ float s_in[NVW * 4];
    load_view_consts(vm, intr, s_vm, s_in);
    int i = blockIdx.x * blockDim.x + threadIdx.x;
    if (i >= n) return;
    float px = g_pw[3*i], py = g_pw[3*i+1], pz = g_pw[3*i+2];
    float na = g_nraw[3*i], nb = g_nraw[3*i+1], nc = g_nraw[3*i+2];
    for (int v = 0; v < NVW; v++) {
        const float* M = &s_vm[v * 12];
        float x = __fadd_rn(dotrow(M,     px, py, pz), M[3]);
        float y = __fadd_rn(dotrow(M + 4, px, py, pz), M[7]);
        float z = __fadd_rn(dotrow(M + 8, px, py, pz), M[11]);
        float zs = (fabsf(z) < 1e-6f) ? 1e-6f : z;
        int u = proj_pix(s_in[v*4+0], s_in[v*4+2], x, zs);
        int w = proj_pix(s_in[v*4+1], s_in[v*4+3], y, zs);
        if (!(z > 0.025f && z < 100.0f && u >= 0 && u < WSZ && w >= 0 && w < HSZ))
            continue;
        int pix = v * NPIX + w * WSZ + u;
        float df = __uint_as_float(g_dflat[pix]);
        if (z <= __fadd_rn(df, 1e-6f)) {
            // nrm = normals_raw @ R.T (no translate), then -nrm / max(|nrm|, 1e-5)
            float rx = dotrow(M,     na, nb, nc);
            float ry = dotrow(M + 4, na, nb, nc);
            float rz = dotrow(M + 8, na, nb, nc);
            float ss = __fadd_rn(__fadd_rn(__fmul_rn(rx, rx), __fmul_rn(ry, ry)),
                                 __fmul_rn(rz, rz));
            float len = fmaxf(__fsqrt_rn(ss), 1e-5f);
            atomicAdd(&g_nsum[3*pix+0], __fdiv_rn(-rx, len));
            atomicAdd(&g_nsum[3*pix+1], __fdiv_rn(-ry, len));
            atomicAdd(&g_nsum[3*pix+2], __fdiv_rn(-rz, len));
            atomicAdd(&g_ncnt[pix], 1.f);
        }
    }
}

// ---------------- reductions: pass A = mins + valid count ------------------
__global__ void k_min(const float* __restrict__ tgt) {
    int v = blockIdx.y;
    int p = blockIdx.x * blockDim.x + threadIdx.x;   // NPIX % 256 == 0
    float df = __uint_as_float(g_dflat[v * NPIX + p]);
    float dimg = (df < 5e29f) ? __fmul_rn(df, 0.04f) : 0.f;
    float dt = tgt[v * NPIX + p];
    unsigned mnd = __float_as_uint(dimg);
    unsigned mnt = __float_as_uint(dt);
    int cnt = (dt != 0.f) ? 1 : 0;
    for (int o = 16; o; o >>= 1) {
        mnd = min(mnd, __shfl_down_sync(0xffffffffu, mnd, o));
        mnt = min(mnt, __shfl_down_sync(0xffffffffu, mnt, o));
        cnt += __shfl_down_sync(0xffffffffu, cnt, o);
    }
    __shared__ unsigned smnd[8], smnt[8];
    __shared__ int sc[8];
    int wid = threadIdx.x >> 5, lid = threadIdx.x & 31;
    if (lid == 0) { smnd[wid]=mnd; smnt[wid]=mnt; sc[wid]=cnt; }
    __syncthreads();
    if (threadIdx.x == 0) {
        for (int w = 1; w < 8; w++) {
            mnd = min(mnd, smnd[w]); mnt = min(mnt, smnt[w]); cnt += sc[w];
        }
        atomicMin(&g_dmin[v], mnd);
        atomicMin(&g_tmin[v], mnt);
        atomicAdd(&g_vcnt[v], cnt);
    }
}

// ---------- pass B = max of shifted (x - min), matching _normalize01 -------
__global__ void k_max(const float* __restrict__ tgt) {
    int v = blockIdx.y;
    int p = blockIdx.x * blockDim.x + threadIdx.x;
    float df = __uint_as_float(g_dflat[v * NPIX + p]);
    float dimg = (df < 5e29f) ? __fmul_rn(df, 0.04f) : 0.f;
    float dt = tgt[v * NPIX + p];
    float sd = __fsub_rn(dimg, __uint_as_float(g_dmin[v]));   // >= 0
    float st = __fsub_rn(dt,   __uint_as_float(g_tmin[v]));   // >= 0
    unsigned mxd = __float_as_uint(sd);
    unsigned mxt = __float_as_uint(st);
    for (int o = 16; o; o >>= 1) {
        mxd = max(mxd, __shfl_down_sync(0xffffffffu, mxd, o));
        mxt = max(mxt, __shfl_down_sync(0xffffffffu, mxt, o));
    }
    __shared__ unsigned smxd[8], smxt[8];
    int wid = threadIdx.x >> 5, lid = threadIdx.x & 31;
    if (lid == 0) { smxd[wid]=mxd; smxt[wid]=mxt; }
    __syncthreads();
    if (threadIdx.x == 0) {
        for (int w = 1; w < 8; w++) { mxd = max(mxd, smxd[w]); mxt = max(mxt, smxt[w]); }
        atomicMax(&g_drng[v], mxd);
        atomicMax(&g_trng[v], mxt);
    }
}

// ---------------- finalize images + partial loss ----------------------------
__global__ void k_final(const float* __restrict__ tgt, float* __restrict__ out) {
    int v = blockIdx.y;
    int p = blockIdx.x * blockDim.x + threadIdx.x;
    int gp = v * NPIX + p;
    float df = __uint_as_float(g_dflat[gp]);
    bool hit = df < 5e29f;
    float dimg = hit ? __fmul_rn(df, 0.04f) : 0.f;
    float sd = __fsub_rn(dimg, __uint_as_float(g_dmin[v]));
    float drg = __uint_as_float(g_drng[v]);
    float dn = (drg != 0.f) ? __fdiv_rn(sd, drg) : sd;
    float dt = tgt[gp];
    float st = __fsub_rn(dt, __uint_as_float(g_tmin[v]));
    float trg = __uint_as_float(g_trng[v]);
    float tn = (trg != 0.f) ? __fdiv_rn(st, trg) : st;
    out[1 + gp] = dn;
    out[1 + NVW * NPIX + gp] = tn;
    float cn = fmaxf(g_ncnt[gp], 1.f);
    float n0 = hit ? __fdiv_rn(g_nsum[3*gp+0], cn) : 0.f;
    float n1 = hit ? __fdiv_rn(g_nsum[3*gp+1], cn) : 0.f;
    float n2 = hit ? __fdiv_rn(g_nsum[3*gp+2], cn) : 0.f;
    out[1 + 2 * NVW * NPIX + 3 * gp + 0] = n0;
    out[1 + 2 * NVW * NPIX + 3 * gp + 1] = n1;
    out[1 + 2 * NVW * NPIX + 3 * gp + 2] = n2;
    float l = (dt != 0.f) ? fabsf(__fsub_rn(dn, tn)) : 0.f;
    for (int o = 16; o; o >>= 1) l += __shfl_down_sync(0xffffffffu, l, o);
    __shared__ float sl[8];
    int wid = threadIdx.x >> 5, lid = threadIdx.x & 31;
    if (lid == 0) sl[wid] = l;
    __syncthreads();
    if (threadIdx.x == 0) {
        for (int w = 1; w < 8; w++) l += sl[w];
        atomicAdd(&g_lsum[v], l);
    }
}

__global__ void k_loss(float* __restrict__ out) {
    if (threadIdx.x == 0) {
        float tot = 0.f;
        for (int v = 0; v < NVW; v++) {
            float c = (float)g_vcnt[v];
            float l = (g_vcnt[v] > 0) ? __fdiv_rn(g_lsum[v], fmaxf(c, 1.f)) : 0.f;
            tot = __fadd_rn(tot, __fdiv_rn(l, 9.0f));   // * WEIGHT(1) / N_VIEWS
        }
        out[0] = tot;
    }
}

// ---------------------------------------------------------------------------
extern "C" void kernel_launch(void* const* d_in, const int* in_sizes, int n_in,
                              void* d_out, int out_size) {
    const int*   coords = (const int*)  d_in[0];
    const float* origin = (const float*)d_in[1];
    const float* sdf    = (const float*)d_in[2];
    // d_in[3] = sdf_target (unused by forward)
    const float* tgt    = (const float*)d_in[4];
    const float* intr   = (const float*)d_in[5];
    const float* vm     = (const float*)d_in[6];
    float* out = (float*)d_out;

    int n = in_sizes[0] / 4;
    if (n > MAXN) n = MAXN;
    const int tb = 256;

    k_init<<<(NVW * NPIX + tb - 1) / tb, tb>>>();
    k_scatter<<<(n + tb - 1) / tb, tb>>>(coords, origin, n);
    k_grid<<<(NCELL + tb - 1) / tb, tb>>>(sdf);
    k_normals<<<(n + tb - 1) / tb, tb>>>(coords, n);
    k_project<<<(n + tb - 1) / tb, tb>>>(vm, intr, n);
    k_splat<<<(n + tb - 1) / tb, tb>>>(vm, intr, n);
    dim3 rg(NPIX / tb, NVW);
    k_min<<<rg, tb>>>(tgt);
    k_max<<<rg, tb>>>(tgt);
    k_final<<<rg, tb>>>(tgt, out);
    k_loss<<<1, 32>>>(out);
}